// round 12
// baseline (speedup 1.0000x reference)
#include <cuda_runtime.h>

#define N_NODES 200000
#define N_EDGES 3200000
#define SCAN_BLOCKS 196   // ceil(200000 / 1024)

// ---------------- scratch (device globals; zero-initialized at module load) ----------------
__device__ __align__(16) int    g_deg[N_NODES];      // invariant: zero at kernel_launch entry
__device__ __align__(16) int    g_off[N_NODES + 1];
__device__ __align__(16) int    g_cursor[N_NODES];
__device__ __align__(16) int    g_flag[256];         // invariant: zero at kernel_launch entry
__device__ __align__(16) int    g_src[N_EDGES];
__device__ __align__(16) float2 g_kw[N_EDGES];
__device__ __align__(16) float  g_h16[N_NODES * 16];
__device__ __align__(16) float  g_h32[N_NODES * 32];
__device__ __align__(16) float  g_h64[N_NODES * 64];

// ---------------- tf32 mma helpers ----------------
__device__ __forceinline__ unsigned f2tf32(float x) {
    unsigned u;
    asm("cvt.rna.tf32.f32 %0, %1;" : "=r"(u) : "f"(x));
    return u;
}
__device__ __forceinline__ void split2(float x, unsigned& hi, unsigned& lo) {
    hi = f2tf32(x);
    lo = f2tf32(x - __uint_as_float(hi));
}
// D(16x8) += A(16x8,row) * B(8x8,col); acc in-place
__device__ __forceinline__ void mma8(float* c, const unsigned* a, const unsigned* b) {
    asm("mma.sync.aligned.m16n8k8.row.col.f32.tf32.tf32.f32 "
        "{%0,%1,%2,%3}, {%4,%5,%6,%7}, {%8,%9}, {%0,%1,%2,%3};"
        : "+f"(c[0]), "+f"(c[1]), "+f"(c[2]), "+f"(c[3])
        : "r"(a[0]), "r"(a[1]), "r"(a[2]), "r"(a[3]), "r"(b[0]), "r"(b[1]));
}

// ---------------- CSR build ----------------
__global__ void k_hist(const int* __restrict__ ei) {
    int e = blockIdx.x * blockDim.x + threadIdx.x;
    if (e < N_EDGES) atomicAdd(&g_deg[ei[N_EDGES + e]], 1);
}

// single-pass scan: block-local scan + spin-flag lookback over earlier blocks.
__global__ void k_scan() {
    __shared__ int sh[256];
    __shared__ int red[8];
    int t = threadIdx.x;
    int b = blockIdx.x;
    int base = b * 1024 + t * 4;
    int v0 = 0, v1 = 0, v2 = 0, v3 = 0;
    if (base + 0 < N_NODES) v0 = g_deg[base + 0];
    if (base + 1 < N_NODES) v1 = g_deg[base + 1];
    if (base + 2 < N_NODES) v2 = g_deg[base + 2];
    if (base + 3 < N_NODES) v3 = g_deg[base + 3];
    int tot = v0 + v1 + v2 + v3;
    sh[t] = tot;
    __syncthreads();
    for (int d = 1; d < 256; d <<= 1) {
        int xv = (t >= d) ? sh[t - d] : 0;
        __syncthreads();
        sh[t] += xv;
        __syncthreads();
    }
    if (t == 255) ((volatile int*)g_flag)[b] = sh[255] + 1;  // publish block total

    int v = 0;
    if (t < b) {
        volatile int* f = (volatile int*)g_flag;
        int fv;
        while ((fv = f[t]) == 0) {}
        v = fv - 1;
    }
#pragma unroll
    for (int d = 16; d > 0; d >>= 1) v += __shfl_down_sync(0xffffffffu, v, d);
    if ((t & 31) == 0) red[t >> 5] = v;
    __syncthreads();
    int prefix = red[0] + red[1] + red[2] + red[3] + red[4] + red[5] + red[6] + red[7];

    int excl = sh[t] - tot + prefix;
    int e0 = excl, e1 = excl + v0, e2 = excl + v0 + v1, e3 = excl + v0 + v1 + v2;
    if (base + 0 < N_NODES) { g_off[base + 0] = e0; g_cursor[base + 0] = e0; g_deg[base + 0] = 0; }
    if (base + 1 < N_NODES) { g_off[base + 1] = e1; g_cursor[base + 1] = e1; g_deg[base + 1] = 0; }
    if (base + 2 < N_NODES) { g_off[base + 2] = e2; g_cursor[base + 2] = e2; g_deg[base + 2] = 0; }
    if (base + 3 < N_NODES) { g_off[base + 3] = e3; g_cursor[base + 3] = e3; g_deg[base + 3] = 0; }
    if (b == 0 && t == 0) g_off[N_NODES] = N_EDGES;
}

__global__ void k_scatter(const int* __restrict__ ei, const float* __restrict__ Kw) {
    int e = blockIdx.x * blockDim.x + threadIdx.x;
    if (e < 256) g_flag[e] = 0;   // restore scan-flag invariant for next replay
    if (e >= N_EDGES) return;
    int s = ei[e];
    int d = ei[N_EDGES + e];
    float k0 = Kw[e];
    float k1 = Kw[N_EDGES + e];
    int p = atomicAdd(&g_cursor[d], 1);
    g_src[p] = s;
    g_kw[p] = make_float2(k0, k1);
}

// ---------------- layer 0: conv (d=8, nk=2) ----------------
__global__ void k_conv0(const float* __restrict__ x) {
    int warp = threadIdx.x >> 5, lane = threadIdx.x & 31;
    int node = blockIdx.x * 8 + warp;
    if (node >= N_NODES) return;
    int f = lane & 7, sub = lane >> 3;
    int beg = g_off[node], end = g_off[node + 1];
    float a0 = 0.f, a1 = 0.f;
    for (int k = beg + sub; k < end; k += 4) {
        int s = g_src[k];
        float2 kw = g_kw[k];
        float xv = x[s * 8 + f];
        a0 = fmaf(kw.x, xv, a0);
        a1 = fmaf(kw.y, xv, a1);
    }
    a0 += __shfl_xor_sync(0xffffffffu, a0, 8);
    a0 += __shfl_xor_sync(0xffffffffu, a0, 16);
    a1 += __shfl_xor_sync(0xffffffffu, a1, 8);
    a1 += __shfl_xor_sync(0xffffffffu, a1, 16);
    if (sub == 0) {
        g_h16[node * 16 + f]     = a0;
        g_h16[node * 16 + 8 + f] = a1;
    }
}

// ---------------- layer 0: MLP 16->32 + L2 norm ----------------
__global__ void k_mlp0(const float* __restrict__ W0, const float* __restrict__ b0) {
    __shared__ float W0s[512];
    __shared__ float b0s[32];
    for (int i = threadIdx.x; i < 512; i += blockDim.x) W0s[i] = W0[i];
    if (threadIdx.x < 32) b0s[threadIdx.x] = b0[threadIdx.x];
    __syncthreads();
    int node = blockIdx.x * blockDim.x + threadIdx.x;
    if (node >= N_NODES) return;
    float h[16];
    const float4* hp = (const float4*)&g_h16[node * 16];
#pragma unroll
    for (int j = 0; j < 4; j++) {
        float4 v = hp[j];
        h[4 * j] = v.x; h[4 * j + 1] = v.y; h[4 * j + 2] = v.z; h[4 * j + 3] = v.w;
    }
    float o[32];
    float ss = 0.f;
#pragma unroll
    for (int j = 0; j < 32; j++) {
        float acc = b0s[j];
#pragma unroll
        for (int i = 0; i < 16; i++) acc = fmaf(h[i], W0s[i * 32 + j], acc);
        o[j] = acc;
        ss += acc * acc;
    }
    float inv = 1.f / fmaxf(sqrtf(ss), 1e-12f);
    float4* op = (float4*)&g_h32[node * 32];
#pragma unroll
    for (int j = 0; j < 8; j++)
        op[j] = make_float4(o[4 * j] * inv, o[4 * j + 1] * inv, o[4 * j + 2] * inv, o[4 * j + 3] * inv);
}

// ---------------- layer 1: conv (d=32, nk=2) ----------------
__global__ void k_conv1() {
    int warp = threadIdx.x >> 5, lane = threadIdx.x & 31;
    int node = blockIdx.x * 8 + warp;
    if (node >= N_NODES) return;
    int beg = g_off[node], end = g_off[node + 1];
    float a0 = 0.f, a1 = 0.f;
    int k = beg;
    for (; k + 4 <= end; k += 4) {
        int s0 = g_src[k], s1 = g_src[k + 1], s2 = g_src[k + 2], s3 = g_src[k + 3];
        float2 w0 = g_kw[k], w1 = g_kw[k + 1], w2 = g_kw[k + 2], w3 = g_kw[k + 3];
        float v0 = g_h32[s0 * 32 + lane];
        float v1 = g_h32[s1 * 32 + lane];
        float v2 = g_h32[s2 * 32 + lane];
        float v3 = g_h32[s3 * 32 + lane];
        a0 = fmaf(w0.x, v0, a0); a1 = fmaf(w0.y, v0, a1);
        a0 = fmaf(w1.x, v1, a0); a1 = fmaf(w1.y, v1, a1);
        a0 = fmaf(w2.x, v2, a0); a1 = fmaf(w2.y, v2, a1);
        a0 = fmaf(w3.x, v3, a0); a1 = fmaf(w3.y, v3, a1);
    }
    for (; k < end; k++) {
        int s = g_src[k];
        float2 w = g_kw[k];
        float v = g_h32[s * 32 + lane];
        a0 = fmaf(w.x, v, a0);
        a1 = fmaf(w.y, v, a1);
    }
    g_h64[node * 64 + lane]      = a0;
    g_h64[node * 64 + 32 + lane] = a1;
}

// ---------------- layer 1 MLP FUSED: 64 -> 128 (ReLU) -> 64 + L2 norm (tf32 x3) ----------
// Pre-split hi/lo smem tiles: inner loops are pure LDS.64 + mma (no cvt on hot path).
// As[n][k], Hs[o][n] stored as uint2{hi,lo}, stride 68 (68 % 16 == 4 -> conflict-free
// LDS.64 under the half-warp rule for both access patterns).
__global__ void __launch_bounds__(256) k_mlp1f(
    const float* __restrict__ W1, const float* __restrict__ b1,
    const float* __restrict__ W2, const float* __restrict__ b2,
    float* __restrict__ out)
{
    extern __shared__ unsigned smem_u[];
    uint2* As = (uint2*)smem_u;            // [64][68]  h tile, pre-split
    uint2* Hs = As + 64 * 68;              // [128][68] hidden tile, pre-split
    float* ssb  = (float*)(Hs + 128 * 68); // [64]
    float* invb = ssb + 64;                // [64]

    int t = threadIdx.x;
    int w = t >> 5, lane = t & 31;
    int gid = lane >> 2, tig = lane & 3;
    int nbase = blockIdx.x * 64;

    // load + split h tile
    for (int idx = t; idx < 64 * 64; idx += 256) {
        int n = idx >> 6, k = idx & 63;
        float v = g_h64[(nbase + n) * 64 + k];
        unsigned hi, lo;
        split2(v, hi, lo);
        As[n * 68 + k] = make_uint2(hi, lo);
    }
    if (t < 64) ssb[t] = 0.f;
    __syncthreads();

    // ---- pass A: h(64) @ W1(64x128) + b1, ReLU -> Hs (split at write) ----
    {
        float acc[8][4];
        float bias0 = b1[16 * w + gid];
        float bias1 = b1[16 * w + gid + 8];
#pragma unroll
        for (int nt = 0; nt < 8; nt++) {
            acc[nt][0] = bias0; acc[nt][1] = bias0;
            acc[nt][2] = bias1; acc[nt][3] = bias1;
        }
#pragma unroll
        for (int ks = 0; ks < 8; ks++) {
            int k0 = ks * 8;
            float a0f = W1[(k0 + tig) * 128 + 16 * w + gid];
            float a1f = W1[(k0 + tig) * 128 + 16 * w + gid + 8];
            float a2f = W1[(k0 + tig + 4) * 128 + 16 * w + gid];
            float a3f = W1[(k0 + tig + 4) * 128 + 16 * w + gid + 8];
            unsigned ahi[4], alo[4];
            split2(a0f, ahi[0], alo[0]); split2(a1f, ahi[1], alo[1]);
            split2(a2f, ahi[2], alo[2]); split2(a3f, ahi[3], alo[3]);
#pragma unroll
            for (int nt = 0; nt < 8; nt++) {
                uint2 p0 = As[(nt * 8 + gid) * 68 + k0 + tig];
                uint2 p1 = As[(nt * 8 + gid) * 68 + k0 + tig + 4];
                unsigned bhi[2] = { p0.x, p1.x };
                unsigned blo[2] = { p0.y, p1.y };
                mma8(acc[nt], alo, bhi);
                mma8(acc[nt], ahi, blo);
                mma8(acc[nt], ahi, bhi);
            }
        }
        // ReLU + split + store pairs as uint4 (16B aligned: indices even)
        int o0 = 16 * w + gid;
#pragma unroll
        for (int nt = 0; nt < 8; nt++) {
            int n = nt * 8 + 2 * tig;
            float v0 = fmaxf(acc[nt][0], 0.f), v1 = fmaxf(acc[nt][1], 0.f);
            float v2 = fmaxf(acc[nt][2], 0.f), v3 = fmaxf(acc[nt][3], 0.f);
            unsigned h0, l0, h1, l1, h2, l2, h3, l3;
            split2(v0, h0, l0); split2(v1, h1, l1);
            split2(v2, h2, l2); split2(v3, h3, l3);
            *(uint4*)&Hs[o0 * 68 + n]       = make_uint4(h0, l0, h1, l1);
            *(uint4*)&Hs[(o0 + 8) * 68 + n] = make_uint4(h2, l2, h3, l3);
        }
    }
    __syncthreads();

    // ---- pass B: hid(128) @ W2(128x64) + b2 -> L2 norm -> out ----
    int ms = (w & 3) * 16;      // m-strip base
    int nh = (w >> 2) * 32;     // node-half offset
    float acc[4][4];
    {
        float bias0 = b2[ms + gid];
        float bias1 = b2[ms + gid + 8];
#pragma unroll
        for (int nt = 0; nt < 4; nt++) {
            acc[nt][0] = bias0; acc[nt][1] = bias0;
            acc[nt][2] = bias1; acc[nt][3] = bias1;
        }
#pragma unroll
        for (int ks = 0; ks < 16; ks++) {
            int k0 = ks * 8;
            float a0f = W2[(k0 + tig) * 64 + ms + gid];
            float a1f = W2[(k0 + tig) * 64 + ms + gid + 8];
            float a2f = W2[(k0 + tig + 4) * 64 + ms + gid];
            float a3f = W2[(k0 + tig + 4) * 64 + ms + gid + 8];
            unsigned ahi[4], alo[4];
            split2(a0f, ahi[0], alo[0]); split2(a1f, ahi[1], alo[1]);
            split2(a2f, ahi[2], alo[2]); split2(a3f, ahi[3], alo[3]);
#pragma unroll
            for (int nt = 0; nt < 4; nt++) {
                int ncol = nh + nt * 8 + gid;
                uint2 q0 = Hs[(k0 + tig) * 68 + ncol];
                uint2 q1 = Hs[(k0 + tig + 4) * 68 + ncol];
                unsigned bhi[2] = { q0.x, q1.x };
                unsigned blo[2] = { q0.y, q1.y };
                mma8(acc[nt], alo, bhi);
                mma8(acc[nt], ahi, blo);
                mma8(acc[nt], ahi, bhi);
            }
        }
    }

    // per-node column sum of squares: shuffle-reduce over gid, smem-atomic over m-strips
#pragma unroll
    for (int nt = 0; nt < 4; nt++) {
        float s0 = acc[nt][0] * acc[nt][0] + acc[nt][2] * acc[nt][2];
        float s1 = acc[nt][1] * acc[nt][1] + acc[nt][3] * acc[nt][3];
        s0 += __shfl_xor_sync(0xffffffffu, s0, 4);
        s1 += __shfl_xor_sync(0xffffffffu, s1, 4);
        s0 += __shfl_xor_sync(0xffffffffu, s0, 8);
        s1 += __shfl_xor_sync(0xffffffffu, s1, 8);
        s0 += __shfl_xor_sync(0xffffffffu, s0, 16);
        s1 += __shfl_xor_sync(0xffffffffu, s1, 16);
        if (gid == 0) {
            atomicAdd(&ssb[nh + nt * 8 + 2 * tig], s0);
            atomicAdd(&ssb[nh + nt * 8 + 2 * tig + 1], s1);
        }
    }
    __syncthreads();
    if (t < 64) invb[t] = 1.f / fmaxf(sqrtf(ssb[t]), 1e-12f);
    __syncthreads();

#pragma unroll
    for (int nt = 0; nt < 4; nt++) {
        int col0 = nh + nt * 8 + 2 * tig;
        float i0 = invb[col0], i1 = invb[col0 + 1];
        int node0 = nbase + col0;
        out[node0 * 64 + ms + gid]           = acc[nt][0] * i0;
        out[(node0 + 1) * 64 + ms + gid]     = acc[nt][1] * i1;
        out[node0 * 64 + ms + gid + 8]       = acc[nt][2] * i0;
        out[(node0 + 1) * 64 + ms + gid + 8] = acc[nt][3] * i1;
    }
}

// ---------------- launch ----------------
extern "C" void kernel_launch(void* const* d_in, const int* in_sizes, int n_in,
                              void* d_out, int out_size) {
    const float* x  = (const float*)d_in[0];
    const int*   ei = (const int*)d_in[1];
    const float* Kw = (const float*)d_in[2];
    const float* W0 = (const float*)d_in[3];
    const float* b0 = (const float*)d_in[4];
    const float* W1 = (const float*)d_in[5];
    const float* b1 = (const float*)d_in[6];
    const float* W2 = (const float*)d_in[7];
    const float* b2 = (const float*)d_in[8];
    float* out = (float*)d_out;

    const int mlp1_smem = (64 * 68 + 128 * 68) * 8 + 128 * 4;  // 104960 B
    cudaFuncSetAttribute(k_mlp1f, cudaFuncAttributeMaxDynamicSharedMemorySize, mlp1_smem);

    k_hist<<<12500, 256>>>(ei);                         // 1
    k_scan<<<SCAN_BLOCKS, 256>>>();                     // 2
    k_scatter<<<12500, 256>>>(ei, Kw);                  // 3
    k_conv0<<<25000, 256>>>(x);                         // 4  <- ncu capture slot
    k_mlp0<<<782, 256>>>(W0, b0);                       // 5
    k_conv1<<<25000, 256>>>();                          // 6
    k_mlp1f<<<3125, 256, mlp1_smem>>>(W1, b1, W2, b2, out);  // 7
}

// round 13
// speedup vs baseline: 1.0787x; 1.0787x over previous
#include <cuda_runtime.h>

#define N_NODES 200000
#define N_EDGES 3200000
#define SCAN_BLOCKS 196   // ceil(200000 / 1024)

// ---------------- scratch (device globals; zero-initialized at module load) ----------------
__device__ __align__(16) int    g_deg[N_NODES];      // invariant: zero at kernel_launch entry
__device__ __align__(16) int    g_off[N_NODES + 1];
__device__ __align__(16) int    g_cursor[N_NODES];
__device__ __align__(16) int    g_flag[256];         // invariant: zero at kernel_launch entry
__device__ __align__(16) int    g_src[N_EDGES];
__device__ __align__(16) float2 g_kw[N_EDGES];
__device__ __align__(16) float  g_h16[N_NODES * 16];
__device__ __align__(16) float  g_h32[N_NODES * 32];

// ---------------- tf32 mma helpers ----------------
__device__ __forceinline__ unsigned f2tf32(float x) {
    unsigned u;
    asm("cvt.rna.tf32.f32 %0, %1;" : "=r"(u) : "f"(x));
    return u;
}
__device__ __forceinline__ void split2(float x, unsigned& hi, unsigned& lo) {
    hi = f2tf32(x);
    lo = f2tf32(x - __uint_as_float(hi));
}
// D(16x8) += A(16x8,row) * B(8x8,col); acc in-place
__device__ __forceinline__ void mma8(float* c, const unsigned* a, const unsigned* b) {
    asm("mma.sync.aligned.m16n8k8.row.col.f32.tf32.tf32.f32 "
        "{%0,%1,%2,%3}, {%4,%5,%6,%7}, {%8,%9}, {%0,%1,%2,%3};"
        : "+f"(c[0]), "+f"(c[1]), "+f"(c[2]), "+f"(c[3])
        : "r"(a[0]), "r"(a[1]), "r"(a[2]), "r"(a[3]), "r"(b[0]), "r"(b[1]));
}

// ---------------- CSR build ----------------
__global__ void k_hist(const int* __restrict__ ei) {
    int e = blockIdx.x * blockDim.x + threadIdx.x;
    if (e < N_EDGES) atomicAdd(&g_deg[ei[N_EDGES + e]], 1);
}

// single-pass scan: block-local scan + spin-flag lookback over earlier blocks.
__global__ void k_scan() {
    __shared__ int sh[256];
    __shared__ int red[8];
    int t = threadIdx.x;
    int b = blockIdx.x;
    int base = b * 1024 + t * 4;
    int v0 = 0, v1 = 0, v2 = 0, v3 = 0;
    if (base + 0 < N_NODES) v0 = g_deg[base + 0];
    if (base + 1 < N_NODES) v1 = g_deg[base + 1];
    if (base + 2 < N_NODES) v2 = g_deg[base + 2];
    if (base + 3 < N_NODES) v3 = g_deg[base + 3];
    int tot = v0 + v1 + v2 + v3;
    sh[t] = tot;
    __syncthreads();
    for (int d = 1; d < 256; d <<= 1) {
        int xv = (t >= d) ? sh[t - d] : 0;
        __syncthreads();
        sh[t] += xv;
        __syncthreads();
    }
    if (t == 255) ((volatile int*)g_flag)[b] = sh[255] + 1;  // publish block total

    int v = 0;
    if (t < b) {
        volatile int* f = (volatile int*)g_flag;
        int fv;
        while ((fv = f[t]) == 0) {}
        v = fv - 1;
    }
#pragma unroll
    for (int d = 16; d > 0; d >>= 1) v += __shfl_down_sync(0xffffffffu, v, d);
    if ((t & 31) == 0) red[t >> 5] = v;
    __syncthreads();
    int prefix = red[0] + red[1] + red[2] + red[3] + red[4] + red[5] + red[6] + red[7];

    int excl = sh[t] - tot + prefix;
    int e0 = excl, e1 = excl + v0, e2 = excl + v0 + v1, e3 = excl + v0 + v1 + v2;
    if (base + 0 < N_NODES) { g_off[base + 0] = e0; g_cursor[base + 0] = e0; g_deg[base + 0] = 0; }
    if (base + 1 < N_NODES) { g_off[base + 1] = e1; g_cursor[base + 1] = e1; g_deg[base + 1] = 0; }
    if (base + 2 < N_NODES) { g_off[base + 2] = e2; g_cursor[base + 2] = e2; g_deg[base + 2] = 0; }
    if (base + 3 < N_NODES) { g_off[base + 3] = e3; g_cursor[base + 3] = e3; g_deg[base + 3] = 0; }
    if (b == 0 && t == 0) g_off[N_NODES] = N_EDGES;
}

__global__ void k_scatter(const int* __restrict__ ei, const float* __restrict__ Kw) {
    int e = blockIdx.x * blockDim.x + threadIdx.x;
    if (e < 256) g_flag[e] = 0;   // restore scan-flag invariant for next replay
    if (e >= N_EDGES) return;
    int s = ei[e];
    int d = ei[N_EDGES + e];
    float k0 = Kw[e];
    float k1 = Kw[N_EDGES + e];
    int p = atomicAdd(&g_cursor[d], 1);
    g_src[p] = s;
    g_kw[p] = make_float2(k0, k1);
}

// ---------------- layer 0: conv (d=8, nk=2) ----------------
__global__ void k_conv0(const float* __restrict__ x) {
    int warp = threadIdx.x >> 5, lane = threadIdx.x & 31;
    int node = blockIdx.x * 8 + warp;
    if (node >= N_NODES) return;
    int f = lane & 7, sub = lane >> 3;
    int beg = g_off[node], end = g_off[node + 1];
    float a0 = 0.f, a1 = 0.f;
    for (int k = beg + sub; k < end; k += 4) {
        int s = g_src[k];
        float2 kw = g_kw[k];
        float xv = x[s * 8 + f];
        a0 = fmaf(kw.x, xv, a0);
        a1 = fmaf(kw.y, xv, a1);
    }
    a0 += __shfl_xor_sync(0xffffffffu, a0, 8);
    a0 += __shfl_xor_sync(0xffffffffu, a0, 16);
    a1 += __shfl_xor_sync(0xffffffffu, a1, 8);
    a1 += __shfl_xor_sync(0xffffffffu, a1, 16);
    if (sub == 0) {
        g_h16[node * 16 + f]     = a0;
        g_h16[node * 16 + 8 + f] = a1;
    }
}

// ---------------- layer 0: MLP 16->32 + L2 norm ----------------
__global__ void k_mlp0(const float* __restrict__ W0, const float* __restrict__ b0) {
    __shared__ float W0s[512];
    __shared__ float b0s[32];
    for (int i = threadIdx.x; i < 512; i += blockDim.x) W0s[i] = W0[i];
    if (threadIdx.x < 32) b0s[threadIdx.x] = b0[threadIdx.x];
    __syncthreads();
    int node = blockIdx.x * blockDim.x + threadIdx.x;
    if (node >= N_NODES) return;
    float h[16];
    const float4* hp = (const float4*)&g_h16[node * 16];
#pragma unroll
    for (int j = 0; j < 4; j++) {
        float4 v = hp[j];
        h[4 * j] = v.x; h[4 * j + 1] = v.y; h[4 * j + 2] = v.z; h[4 * j + 3] = v.w;
    }
    float o[32];
    float ss = 0.f;
#pragma unroll
    for (int j = 0; j < 32; j++) {
        float acc = b0s[j];
#pragma unroll
        for (int i = 0; i < 16; i++) acc = fmaf(h[i], W0s[i * 32 + j], acc);
        o[j] = acc;
        ss += acc * acc;
    }
    float inv = 1.f / fmaxf(sqrtf(ss), 1e-12f);
    float4* op = (float4*)&g_h32[node * 32];
#pragma unroll
    for (int j = 0; j < 8; j++)
        op[j] = make_float4(o[4 * j] * inv, o[4 * j + 1] * inv, o[4 * j + 2] * inv, o[4 * j + 3] * inv);
}

// ---------------- layer 1 FUSED: conv(d=32,nk=2) -> 64->128 ReLU -> 128->64 + L2 norm ----
// 64-node tile per block, 8 warps, tf32 x3 compensated mma.
// Phase 0: warp w gathers+convolves nodes [nbase+8w, nbase+8w+8) -> As smem (no g_h64).
// Pass A: warp w -> output rows [16w,16w+16) x 64 nodes, ReLU -> Hs.
// Pass B: warp w -> m-strip (w%4)*16, node-half (w/4)*32; per-node column L2 norm.
__global__ void __launch_bounds__(256) k_l1fused(
    const float* __restrict__ W1, const float* __restrict__ b1,
    const float* __restrict__ W2, const float* __restrict__ b2,
    float* __restrict__ out)
{
    extern __shared__ float smem[];
    float* As  = smem;                    // [64][68]  h tile (stride 68)
    float* Hs  = smem + 64 * 68;          // [128][68] hidden tile (stride 68)
    float* ssb = smem + 64 * 68 + 128 * 68;  // [64]
    float* invb = ssb + 64;               // [64]

    int t = threadIdx.x;
    int w = t >> 5, lane = t & 31;
    int gid = lane >> 2, tig = lane & 3;
    int nbase = blockIdx.x * 64;

    // ---- phase 0: conv1 into As ----
    {
#pragma unroll 1
        for (int i = 0; i < 8; i++) {
            int n = w * 8 + i;
            int node = nbase + n;
            int beg = g_off[node], end = g_off[node + 1];
            float a0 = 0.f, a1 = 0.f;
            int k = beg;
            for (; k + 4 <= end; k += 4) {
                int s0 = g_src[k], s1 = g_src[k + 1], s2 = g_src[k + 2], s3 = g_src[k + 3];
                float2 w0 = g_kw[k], w1 = g_kw[k + 1], w2 = g_kw[k + 2], w3 = g_kw[k + 3];
                float v0 = g_h32[s0 * 32 + lane];
                float v1 = g_h32[s1 * 32 + lane];
                float v2 = g_h32[s2 * 32 + lane];
                float v3 = g_h32[s3 * 32 + lane];
                a0 = fmaf(w0.x, v0, a0); a1 = fmaf(w0.y, v0, a1);
                a0 = fmaf(w1.x, v1, a0); a1 = fmaf(w1.y, v1, a1);
                a0 = fmaf(w2.x, v2, a0); a1 = fmaf(w2.y, v2, a1);
                a0 = fmaf(w3.x, v3, a0); a1 = fmaf(w3.y, v3, a1);
            }
            for (; k < end; k++) {
                int s = g_src[k];
                float2 kw = g_kw[k];
                float v = g_h32[s * 32 + lane];
                a0 = fmaf(kw.x, v, a0);
                a1 = fmaf(kw.y, v, a1);
            }
            As[n * 68 + lane]      = a0;
            As[n * 68 + 32 + lane] = a1;
        }
    }
    if (t < 64) ssb[t] = 0.f;
    __syncthreads();

    // ---- pass A: h(64) @ W1(64x128) + b1, ReLU -> Hs ----
    {
        float acc[8][4];
        float bias0 = b1[16 * w + gid];
        float bias1 = b1[16 * w + gid + 8];
#pragma unroll
        for (int nt = 0; nt < 8; nt++) {
            acc[nt][0] = bias0; acc[nt][1] = bias0;
            acc[nt][2] = bias1; acc[nt][3] = bias1;
        }
#pragma unroll
        for (int ks = 0; ks < 8; ks++) {
            int k0 = ks * 8;
            float a0f = W1[(k0 + tig) * 128 + 16 * w + gid];
            float a1f = W1[(k0 + tig) * 128 + 16 * w + gid + 8];
            float a2f = W1[(k0 + tig + 4) * 128 + 16 * w + gid];
            float a3f = W1[(k0 + tig + 4) * 128 + 16 * w + gid + 8];
            unsigned ahi[4], alo[4];
            split2(a0f, ahi[0], alo[0]); split2(a1f, ahi[1], alo[1]);
            split2(a2f, ahi[2], alo[2]); split2(a3f, ahi[3], alo[3]);
#pragma unroll
            for (int nt = 0; nt < 8; nt++) {
                float b0f = As[(nt * 8 + gid) * 68 + k0 + tig];
                float b1f = As[(nt * 8 + gid) * 68 + k0 + tig + 4];
                unsigned bhi[2], blo[2];
                split2(b0f, bhi[0], blo[0]); split2(b1f, bhi[1], blo[1]);
                mma8(acc[nt], alo, bhi);
                mma8(acc[nt], ahi, blo);
                mma8(acc[nt], ahi, bhi);
            }
        }
        // ReLU -> Hs[o][node] (stride 68); pairs are 8B-aligned (even offsets)
        int o0 = 16 * w + gid;
#pragma unroll
        for (int nt = 0; nt < 8; nt++) {
            int n = nt * 8 + 2 * tig;
            *(float2*)&Hs[o0 * 68 + n] =
                make_float2(fmaxf(acc[nt][0], 0.f), fmaxf(acc[nt][1], 0.f));
            *(float2*)&Hs[(o0 + 8) * 68 + n] =
                make_float2(fmaxf(acc[nt][2], 0.f), fmaxf(acc[nt][3], 0.f));
        }
    }
    __syncthreads();

    // ---- pass B: hid(128) @ W2(128x64) + b2 -> L2 norm -> out ----
    int ms = (w & 3) * 16;      // m-strip base
    int nh = (w >> 2) * 32;     // node-half offset
    float acc[4][4];
    {
        float bias0 = b2[ms + gid];
        float bias1 = b2[ms + gid + 8];
#pragma unroll
        for (int nt = 0; nt < 4; nt++) {
            acc[nt][0] = bias0; acc[nt][1] = bias0;
            acc[nt][2] = bias1; acc[nt][3] = bias1;
        }
#pragma unroll
        for (int ks = 0; ks < 16; ks++) {
            int k0 = ks * 8;
            float a0f = W2[(k0 + tig) * 64 + ms + gid];
            float a1f = W2[(k0 + tig) * 64 + ms + gid + 8];
            float a2f = W2[(k0 + tig + 4) * 64 + ms + gid];
            float a3f = W2[(k0 + tig + 4) * 64 + ms + gid + 8];
            unsigned ahi[4], alo[4];
            split2(a0f, ahi[0], alo[0]); split2(a1f, ahi[1], alo[1]);
            split2(a2f, ahi[2], alo[2]); split2(a3f, ahi[3], alo[3]);
#pragma unroll
            for (int nt = 0; nt < 4; nt++) {
                int ncol = nh + nt * 8 + gid;
                float b0f = Hs[(k0 + tig) * 68 + ncol];
                float b1f = Hs[(k0 + tig + 4) * 68 + ncol];
                unsigned bhi[2], blo[2];
                split2(b0f, bhi[0], blo[0]); split2(b1f, bhi[1], blo[1]);
                mma8(acc[nt], alo, bhi);
                mma8(acc[nt], ahi, blo);
                mma8(acc[nt], ahi, bhi);
            }
        }
    }

    // per-node column sum of squares: shuffle-reduce over gid, smem-atomic over m-strips
#pragma unroll
    for (int nt = 0; nt < 4; nt++) {
        float s0 = acc[nt][0] * acc[nt][0] + acc[nt][2] * acc[nt][2];
        float s1 = acc[nt][1] * acc[nt][1] + acc[nt][3] * acc[nt][3];
        s0 += __shfl_xor_sync(0xffffffffu, s0, 4);
        s1 += __shfl_xor_sync(0xffffffffu, s1, 4);
        s0 += __shfl_xor_sync(0xffffffffu, s0, 8);
        s1 += __shfl_xor_sync(0xffffffffu, s1, 8);
        s0 += __shfl_xor_sync(0xffffffffu, s0, 16);
        s1 += __shfl_xor_sync(0xffffffffu, s1, 16);
        if (gid == 0) {
            atomicAdd(&ssb[nh + nt * 8 + 2 * tig], s0);
            atomicAdd(&ssb[nh + nt * 8 + 2 * tig + 1], s1);
        }
    }
    __syncthreads();
    if (t < 64) invb[t] = 1.f / fmaxf(sqrtf(ssb[t]), 1e-12f);
    __syncthreads();

#pragma unroll
    for (int nt = 0; nt < 4; nt++) {
        int col0 = nh + nt * 8 + 2 * tig;
        float i0 = invb[col0], i1 = invb[col0 + 1];
        int node0 = nbase + col0;
        out[node0 * 64 + ms + gid]           = acc[nt][0] * i0;
        out[(node0 + 1) * 64 + ms + gid]     = acc[nt][1] * i1;
        out[node0 * 64 + ms + gid + 8]       = acc[nt][2] * i0;
        out[(node0 + 1) * 64 + ms + gid + 8] = acc[nt][3] * i1;
    }
}

// ---------------- launch ----------------
extern "C" void kernel_launch(void* const* d_in, const int* in_sizes, int n_in,
                              void* d_out, int out_size) {
    const float* x  = (const float*)d_in[0];
    const int*   ei = (const int*)d_in[1];
    const float* Kw = (const float*)d_in[2];
    const float* W0 = (const float*)d_in[3];
    const float* b0 = (const float*)d_in[4];
    const float* W1 = (const float*)d_in[5];
    const float* b1 = (const float*)d_in[6];
    const float* W2 = (const float*)d_in[7];
    const float* b2 = (const float*)d_in[8];
    float* out = (float*)d_out;

    const int l1_smem = (64 * 68 + 128 * 68 + 128) * 4;  // 52736 B
    cudaFuncSetAttribute(k_l1fused, cudaFuncAttributeMaxDynamicSharedMemorySize, l1_smem);

    k_hist<<<12500, 256>>>(ei);                         // 1
    k_scan<<<SCAN_BLOCKS, 256>>>();                     // 2
    k_scatter<<<12500, 256>>>(ei, Kw);                  // 3
    k_conv0<<<25000, 256>>>(x);                         // 4  <- ncu capture slot
    k_mlp0<<<782, 256>>>(W0, b0);                       // 5
    k_l1fused<<<3125, 256, l1_smem>>>(W1, b1, W2, b2, out);  // 6
}

// round 14
// speedup vs baseline: 1.1132x; 1.0320x over previous
#include <cuda_runtime.h>

#define N_NODES 200000
#define N_EDGES 3200000
#define SCAN_BLOCKS 196   // ceil(200000 / 1024)

// ---------------- scratch (device globals; zero-initialized at module load) ----------------
__device__ __align__(16) int    g_deg[N_NODES];      // invariant: zero at kernel_launch entry
__device__ __align__(16) int    g_off[N_NODES + 1];
__device__ __align__(16) int    g_cursor[N_NODES];
__device__ __align__(16) int    g_flag[256];         // invariant: zero at kernel_launch entry
__device__ __align__(16) int    g_src[N_EDGES];
__device__ __align__(16) float2 g_kw[N_EDGES];
__device__ __align__(16) float  g_h16[N_NODES * 16];
__device__ __align__(16) float  g_h32[N_NODES * 32];
__device__ __align__(16) uint2  g_W1s[64 * 128];     // W1 pre-split {hi,lo}
__device__ __align__(16) uint2  g_W2s[128 * 64];     // W2 pre-split {hi,lo}

// ---------------- tf32 mma helpers ----------------
__device__ __forceinline__ unsigned f2tf32(float x) {
    unsigned u;
    asm("cvt.rna.tf32.f32 %0, %1;" : "=r"(u) : "f"(x));
    return u;
}
__device__ __forceinline__ void split2(float x, unsigned& hi, unsigned& lo) {
    hi = f2tf32(x);
    lo = f2tf32(x - __uint_as_float(hi));
}
// D(16x8) += A(16x8,row) * B(8x8,col); acc in-place
__device__ __forceinline__ void mma8(float* c, const unsigned* a, const unsigned* b) {
    asm("mma.sync.aligned.m16n8k8.row.col.f32.tf32.tf32.f32 "
        "{%0,%1,%2,%3}, {%4,%5,%6,%7}, {%8,%9}, {%0,%1,%2,%3};"
        : "+f"(c[0]), "+f"(c[1]), "+f"(c[2]), "+f"(c[3])
        : "r"(a[0]), "r"(a[1]), "r"(a[2]), "r"(a[3]), "r"(b[0]), "r"(b[1]));
}

// ---------------- weight pre-split (runs once per launch; 3µs) ----------------
__global__ void k_wsplit(const float* __restrict__ W1, const float* __restrict__ W2) {
    int i = blockIdx.x * 256 + threadIdx.x;
    if (i < 64 * 128) {
        unsigned h, l;
        split2(W1[i], h, l);
        g_W1s[i] = make_uint2(h, l);
    }
    if (i < 128 * 64) {
        unsigned h, l;
        split2(W2[i], h, l);
        g_W2s[i] = make_uint2(h, l);
    }
}

// ---------------- CSR build ----------------
__global__ void k_hist(const int* __restrict__ ei) {
    int e = blockIdx.x * blockDim.x + threadIdx.x;
    if (e < N_EDGES) atomicAdd(&g_deg[ei[N_EDGES + e]], 1);
}

// single-pass scan: block-local scan + spin-flag lookback over earlier blocks.
__global__ void k_scan() {
    __shared__ int sh[256];
    __shared__ int red[8];
    int t = threadIdx.x;
    int b = blockIdx.x;
    int base = b * 1024 + t * 4;
    int v0 = 0, v1 = 0, v2 = 0, v3 = 0;
    if (base + 0 < N_NODES) v0 = g_deg[base + 0];
    if (base + 1 < N_NODES) v1 = g_deg[base + 1];
    if (base + 2 < N_NODES) v2 = g_deg[base + 2];
    if (base + 3 < N_NODES) v3 = g_deg[base + 3];
    int tot = v0 + v1 + v2 + v3;
    sh[t] = tot;
    __syncthreads();
    for (int d = 1; d < 256; d <<= 1) {
        int xv = (t >= d) ? sh[t - d] : 0;
        __syncthreads();
        sh[t] += xv;
        __syncthreads();
    }
    if (t == 255) ((volatile int*)g_flag)[b] = sh[255] + 1;  // publish block total

    int v = 0;
    if (t < b) {
        volatile int* f = (volatile int*)g_flag;
        int fv;
        while ((fv = f[t]) == 0) {}
        v = fv - 1;
    }
#pragma unroll
    for (int d = 16; d > 0; d >>= 1) v += __shfl_down_sync(0xffffffffu, v, d);
    if ((t & 31) == 0) red[t >> 5] = v;
    __syncthreads();
    int prefix = red[0] + red[1] + red[2] + red[3] + red[4] + red[5] + red[6] + red[7];

    int excl = sh[t] - tot + prefix;
    int e0 = excl, e1 = excl + v0, e2 = excl + v0 + v1, e3 = excl + v0 + v1 + v2;
    if (base + 0 < N_NODES) { g_off[base + 0] = e0; g_cursor[base + 0] = e0; g_deg[base + 0] = 0; }
    if (base + 1 < N_NODES) { g_off[base + 1] = e1; g_cursor[base + 1] = e1; g_deg[base + 1] = 0; }
    if (base + 2 < N_NODES) { g_off[base + 2] = e2; g_cursor[base + 2] = e2; g_deg[base + 2] = 0; }
    if (base + 3 < N_NODES) { g_off[base + 3] = e3; g_cursor[base + 3] = e3; g_deg[base + 3] = 0; }
    if (b == 0 && t == 0) g_off[N_NODES] = N_EDGES;
}

__global__ void k_scatter(const int* __restrict__ ei, const float* __restrict__ Kw) {
    int e = blockIdx.x * blockDim.x + threadIdx.x;
    if (e < 256) g_flag[e] = 0;   // restore scan-flag invariant for next replay
    if (e >= N_EDGES) return;
    int s = ei[e];
    int d = ei[N_EDGES + e];
    float k0 = Kw[e];
    float k1 = Kw[N_EDGES + e];
    int p = atomicAdd(&g_cursor[d], 1);
    g_src[p] = s;
    g_kw[p] = make_float2(k0, k1);
}

// ---------------- layer 0: conv (d=8, nk=2) ----------------
__global__ void k_conv0(const float* __restrict__ x) {
    int warp = threadIdx.x >> 5, lane = threadIdx.x & 31;
    int node = blockIdx.x * 8 + warp;
    if (node >= N_NODES) return;
    int f = lane & 7, sub = lane >> 3;
    int beg = g_off[node], end = g_off[node + 1];
    float a0 = 0.f, a1 = 0.f;
    for (int k = beg + sub; k < end; k += 4) {
        int s = g_src[k];
        float2 kw = g_kw[k];
        float xv = x[s * 8 + f];
        a0 = fmaf(kw.x, xv, a0);
        a1 = fmaf(kw.y, xv, a1);
    }
    a0 += __shfl_xor_sync(0xffffffffu, a0, 8);
    a0 += __shfl_xor_sync(0xffffffffu, a0, 16);
    a1 += __shfl_xor_sync(0xffffffffu, a1, 8);
    a1 += __shfl_xor_sync(0xffffffffu, a1, 16);
    if (sub == 0) {
        g_h16[node * 16 + f]     = a0;
        g_h16[node * 16 + 8 + f] = a1;
    }
}

// ---------------- layer 0: MLP 16->32 + L2 norm ----------------
__global__ void k_mlp0(const float* __restrict__ W0, const float* __restrict__ b0) {
    __shared__ float W0s[512];
    __shared__ float b0s[32];
    for (int i = threadIdx.x; i < 512; i += blockDim.x) W0s[i] = W0[i];
    if (threadIdx.x < 32) b0s[threadIdx.x] = b0[threadIdx.x];
    __syncthreads();
    int node = blockIdx.x * blockDim.x + threadIdx.x;
    if (node >= N_NODES) return;
    float h[16];
    const float4* hp = (const float4*)&g_h16[node * 16];
#pragma unroll
    for (int j = 0; j < 4; j++) {
        float4 v = hp[j];
        h[4 * j] = v.x; h[4 * j + 1] = v.y; h[4 * j + 2] = v.z; h[4 * j + 3] = v.w;
    }
    float o[32];
    float ss = 0.f;
#pragma unroll
    for (int j = 0; j < 32; j++) {
        float acc = b0s[j];
#pragma unroll
        for (int i = 0; i < 16; i++) acc = fmaf(h[i], W0s[i * 32 + j], acc);
        o[j] = acc;
        ss += acc * acc;
    }
    float inv = 1.f / fmaxf(sqrtf(ss), 1e-12f);
    float4* op = (float4*)&g_h32[node * 32];
#pragma unroll
    for (int j = 0; j < 8; j++)
        op[j] = make_float4(o[4 * j] * inv, o[4 * j + 1] * inv, o[4 * j + 2] * inv, o[4 * j + 3] * inv);
}

// ---------------- layer 1 FUSED: conv(d=32,nk=2) -> 64->128 ReLU -> 128->64 + L2 norm ----
// 64-node tile per block, 8 warps, tf32 x3 compensated mma, pre-split weights.
// Phase 0: warp w convolves its 8 nodes in PAIRS (zipped edge loops, 8 gathers in flight).
// Pass A: warp w -> output rows [16w,16w+16) x 64 nodes, ReLU -> Hs.
// Pass B: warp w -> m-strip (w%4)*16, node-half (w/4)*32; per-node column L2 norm.
__global__ void __launch_bounds__(256) k_l1fused(
    const float* __restrict__ b1, const float* __restrict__ b2,
    float* __restrict__ out)
{
    extern __shared__ float smem[];
    float* As  = smem;                    // [64][68]  h tile (stride 68)
    float* Hs  = smem + 64 * 68;          // [128][68] hidden tile (stride 68)
    float* ssb = smem + 64 * 68 + 128 * 68;  // [64]
    float* invb = ssb + 64;               // [64]

    int t = threadIdx.x;
    int w = t >> 5, lane = t & 31;
    int gid = lane >> 2, tig = lane & 3;
    int nbase = blockIdx.x * 64;

    // ---- phase 0: conv1 into As, node pairs zipped for 8-deep MLP ----
    {
#pragma unroll 1
        for (int i = 0; i < 8; i += 2) {
            int nA = w * 8 + i, nB = nA + 1;
            int kA = g_off[nbase + nA], eA = g_off[nbase + nA + 1];
            int kB = g_off[nbase + nB], eB = g_off[nbase + nB + 1];
            float a0 = 0.f, a1 = 0.f, c0 = 0.f, c1 = 0.f;
            while (kA + 4 <= eA && kB + 4 <= eB) {
                int sA0 = g_src[kA], sA1 = g_src[kA + 1], sA2 = g_src[kA + 2], sA3 = g_src[kA + 3];
                int sB0 = g_src[kB], sB1 = g_src[kB + 1], sB2 = g_src[kB + 2], sB3 = g_src[kB + 3];
                float2 wA0 = g_kw[kA], wA1 = g_kw[kA + 1], wA2 = g_kw[kA + 2], wA3 = g_kw[kA + 3];
                float2 wB0 = g_kw[kB], wB1 = g_kw[kB + 1], wB2 = g_kw[kB + 2], wB3 = g_kw[kB + 3];
                float vA0 = g_h32[sA0 * 32 + lane];
                float vA1 = g_h32[sA1 * 32 + lane];
                float vA2 = g_h32[sA2 * 32 + lane];
                float vA3 = g_h32[sA3 * 32 + lane];
                float vB0 = g_h32[sB0 * 32 + lane];
                float vB1 = g_h32[sB1 * 32 + lane];
                float vB2 = g_h32[sB2 * 32 + lane];
                float vB3 = g_h32[sB3 * 32 + lane];
                a0 = fmaf(wA0.x, vA0, a0); a1 = fmaf(wA0.y, vA0, a1);
                a0 = fmaf(wA1.x, vA1, a0); a1 = fmaf(wA1.y, vA1, a1);
                a0 = fmaf(wA2.x, vA2, a0); a1 = fmaf(wA2.y, vA2, a1);
                a0 = fmaf(wA3.x, vA3, a0); a1 = fmaf(wA3.y, vA3, a1);
                c0 = fmaf(wB0.x, vB0, c0); c1 = fmaf(wB0.y, vB0, c1);
                c0 = fmaf(wB1.x, vB1, c0); c1 = fmaf(wB1.y, vB1, c1);
                c0 = fmaf(wB2.x, vB2, c0); c1 = fmaf(wB2.y, vB2, c1);
                c0 = fmaf(wB3.x, vB3, c0); c1 = fmaf(wB3.y, vB3, c1);
                kA += 4; kB += 4;
            }
            for (; kA + 4 <= eA; kA += 4) {
                int s0 = g_src[kA], s1 = g_src[kA + 1], s2 = g_src[kA + 2], s3 = g_src[kA + 3];
                float2 w0 = g_kw[kA], w1 = g_kw[kA + 1], w2 = g_kw[kA + 2], w3 = g_kw[kA + 3];
                float v0 = g_h32[s0 * 32 + lane];
                float v1 = g_h32[s1 * 32 + lane];
                float v2 = g_h32[s2 * 32 + lane];
                float v3 = g_h32[s3 * 32 + lane];
                a0 = fmaf(w0.x, v0, a0); a1 = fmaf(w0.y, v0, a1);
                a0 = fmaf(w1.x, v1, a0); a1 = fmaf(w1.y, v1, a1);
                a0 = fmaf(w2.x, v2, a0); a1 = fmaf(w2.y, v2, a1);
                a0 = fmaf(w3.x, v3, a0); a1 = fmaf(w3.y, v3, a1);
            }
            for (; kA < eA; kA++) {
                int s = g_src[kA];
                float2 kw = g_kw[kA];
                float v = g_h32[s * 32 + lane];
                a0 = fmaf(kw.x, v, a0);
                a1 = fmaf(kw.y, v, a1);
            }
            for (; kB + 4 <= eB; kB += 4) {
                int s0 = g_src[kB], s1 = g_src[kB + 1], s2 = g_src[kB + 2], s3 = g_src[kB + 3];
                float2 w0 = g_kw[kB], w1 = g_kw[kB + 1], w2 = g_kw[kB + 2], w3 = g_kw[kB + 3];
                float v0 = g_h32[s0 * 32 + lane];
                float v1 = g_h32[s1 * 32 + lane];
                float v2 = g_h32[s2 * 32 + lane];
                float v3 = g_h32[s3 * 32 + lane];
                c0 = fmaf(w0.x, v0, c0); c1 = fmaf(w0.y, v0, c1);
                c0 = fmaf(w1.x, v1, c0); c1 = fmaf(w1.y, v1, c1);
                c0 = fmaf(w2.x, v2, c0); c1 = fmaf(w2.y, v2, c1);
                c0 = fmaf(w3.x, v3, c0); c1 = fmaf(w3.y, v3, c1);
            }
            for (; kB < eB; kB++) {
                int s = g_src[kB];
                float2 kw = g_kw[kB];
                float v = g_h32[s * 32 + lane];
                c0 = fmaf(kw.x, v, c0);
                c1 = fmaf(kw.y, v, c1);
            }
            As[nA * 68 + lane]      = a0;
            As[nA * 68 + 32 + lane] = a1;
            As[nB * 68 + lane]      = c0;
            As[nB * 68 + 32 + lane] = c1;
        }
    }
    if (t < 64) ssb[t] = 0.f;
    __syncthreads();

    // ---- pass A: h(64) @ W1(64x128) + b1, ReLU -> Hs ----
    {
        float acc[8][4];
        int o0 = 16 * w + gid;
        float bias0 = b1[o0];
        float bias1 = b1[o0 + 8];
#pragma unroll
        for (int nt = 0; nt < 8; nt++) {
            acc[nt][0] = bias0; acc[nt][1] = bias0;
            acc[nt][2] = bias1; acc[nt][3] = bias1;
        }
#pragma unroll
        for (int ks = 0; ks < 8; ks++) {
            int k0 = ks * 8;
            uint2 wa0 = g_W1s[(k0 + tig) * 128 + o0];
            uint2 wa1 = g_W1s[(k0 + tig) * 128 + o0 + 8];
            uint2 wa2 = g_W1s[(k0 + tig + 4) * 128 + o0];
            uint2 wa3 = g_W1s[(k0 + tig + 4) * 128 + o0 + 8];
            unsigned ahi[4] = { wa0.x, wa1.x, wa2.x, wa3.x };
            unsigned alo[4] = { wa0.y, wa1.y, wa2.y, wa3.y };
#pragma unroll
            for (int nt = 0; nt < 8; nt++) {
                float b0f = As[(nt * 8 + gid) * 68 + k0 + tig];
                float b1f = As[(nt * 8 + gid) * 68 + k0 + tig + 4];
                unsigned bhi[2], blo[2];
                split2(b0f, bhi[0], blo[0]); split2(b1f, bhi[1], blo[1]);
                mma8(acc[nt], alo, bhi);
                mma8(acc[nt], ahi, blo);
                mma8(acc[nt], ahi, bhi);
            }
        }
        // ReLU -> Hs[o][node] (stride 68); pairs are 8B-aligned (even offsets)
#pragma unroll
        for (int nt = 0; nt < 8; nt++) {
            int n = nt * 8 + 2 * tig;
            *(float2*)&Hs[o0 * 68 + n] =
                make_float2(fmaxf(acc[nt][0], 0.f), fmaxf(acc[nt][1], 0.f));
            *(float2*)&Hs[(o0 + 8) * 68 + n] =
                make_float2(fmaxf(acc[nt][2], 0.f), fmaxf(acc[nt][3], 0.f));
        }
    }
    __syncthreads();

    // ---- pass B: hid(128) @ W2(128x64) + b2 -> L2 norm -> out ----
    int ms = (w & 3) * 16;      // m-strip base
    int nh = (w >> 2) * 32;     // node-half offset
    float acc[4][4];
    {
        float bias0 = b2[ms + gid];
        float bias1 = b2[ms + gid + 8];
#pragma unroll
        for (int nt = 0; nt < 4; nt++) {
            acc[nt][0] = bias0; acc[nt][1] = bias0;
            acc[nt][2] = bias1; acc[nt][3] = bias1;
        }
#pragma unroll
        for (int ks = 0; ks < 16; ks++) {
            int k0 = ks * 8;
            uint2 wa0 = g_W2s[(k0 + tig) * 64 + ms + gid];
            uint2 wa1 = g_W2s[(k0 + tig) * 64 + ms + gid + 8];
            uint2 wa2 = g_W2s[(k0 + tig + 4) * 64 + ms + gid];
            uint2 wa3 = g_W2s[(k0 + tig + 4) * 64 + ms + gid + 8];
            unsigned ahi[4] = { wa0.x, wa1.x, wa2.x, wa3.x };
            unsigned alo[4] = { wa0.y, wa1.y, wa2.y, wa3.y };
#pragma unroll
            for (int nt = 0; nt < 4; nt++) {
                int ncol = nh + nt * 8 + gid;
                float b0f = Hs[(k0 + tig) * 68 + ncol];
                float b1f = Hs[(k0 + tig + 4) * 68 + ncol];
                unsigned bhi[2], blo[2];
                split2(b0f, bhi[0], blo[0]); split2(b1f, bhi[1], blo[1]);
                mma8(acc[nt], alo, bhi);
                mma8(acc[nt], ahi, blo);
                mma8(acc[nt], ahi, bhi);
            }
        }
    }

    // per-node column sum of squares: shuffle-reduce over gid, smem-atomic over m-strips
#pragma unroll
    for (int nt = 0; nt < 4; nt++) {
        float s0 = acc[nt][0] * acc[nt][0] + acc[nt][2] * acc[nt][2];
        float s1 = acc[nt][1] * acc[nt][1] + acc[nt][3] * acc[nt][3];
        s0 += __shfl_xor_sync(0xffffffffu, s0, 4);
        s1 += __shfl_xor_sync(0xffffffffu, s1, 4);
        s0 += __shfl_xor_sync(0xffffffffu, s0, 8);
        s1 += __shfl_xor_sync(0xffffffffu, s1, 8);
        s0 += __shfl_xor_sync(0xffffffffu, s0, 16);
        s1 += __shfl_xor_sync(0xffffffffu, s1, 16);
        if (gid == 0) {
            atomicAdd(&ssb[nh + nt * 8 + 2 * tig], s0);
            atomicAdd(&ssb[nh + nt * 8 + 2 * tig + 1], s1);
        }
    }
    __syncthreads();
    if (t < 64) invb[t] = 1.f / fmaxf(sqrtf(ssb[t]), 1e-12f);
    __syncthreads();

#pragma unroll
    for (int nt = 0; nt < 4; nt++) {
        int col0 = nh + nt * 8 + 2 * tig;
        float i0 = invb[col0], i1 = invb[col0 + 1];
        int node0 = nbase + col0;
        out[node0 * 64 + ms + gid]           = acc[nt][0] * i0;
        out[(node0 + 1) * 64 + ms + gid]     = acc[nt][1] * i1;
        out[node0 * 64 + ms + gid + 8]       = acc[nt][2] * i0;
        out[(node0 + 1) * 64 + ms + gid + 8] = acc[nt][3] * i1;
    }
}

// ---------------- launch ----------------
extern "C" void kernel_launch(void* const* d_in, const int* in_sizes, int n_in,
                              void* d_out, int out_size) {
    const float* x  = (const float*)d_in[0];
    const int*   ei = (const int*)d_in[1];
    const float* Kw = (const float*)d_in[2];
    const float* W0 = (const float*)d_in[3];
    const float* b0 = (const float*)d_in[4];
    const float* W1 = (const float*)d_in[5];
    const float* b1 = (const float*)d_in[6];
    const float* W2 = (const float*)d_in[7];
    const float* b2 = (const float*)d_in[8];
    float* out = (float*)d_out;

    const int l1_smem = (64 * 68 + 128 * 68 + 128) * 4;  // 52736 B
    cudaFuncSetAttribute(k_l1fused, cudaFuncAttributeMaxDynamicSharedMemorySize, l1_smem);

    k_hist<<<12500, 256>>>(ei);                         // 1
    k_scan<<<SCAN_BLOCKS, 256>>>();                     // 2
    k_scatter<<<12500, 256>>>(ei, Kw);                  // 3
    k_conv0<<<25000, 256>>>(x);                         // 4  <- ncu capture slot
    k_mlp0<<<391, 512>>>(W0, b0);                       // 5
    k_wsplit<<<32, 256>>>(W1, W2);                      // 6
    k_l1fused<<<3125, 256, l1_smem>>>(b1, b2, out);     // 7
}